// round 5
// baseline (speedup 1.0000x reference)
#include <cuda_runtime.h>

#define TT 128   // decodelen
#define BB 512   // batch
#define EE 128   // entity size
#define NEVT 16  // lse accumulations (15 boundaries + terminal)
#define NB 4     // batches per block
#define L2E 1.4426950408889634f
#define LN2 0.6931471805599453f

__device__ float g_partial[BB];

// ---------------------------------------------------------------------------
__device__ __forceinline__ void ffma2(unsigned long long &d,
                                      unsigned long long a,
                                      unsigned long long b) {
    asm("fma.rn.f32x2 %0, %1, %2, %0;" : "+l"(d) : "l"(a), "l"(b));
}
__device__ __forceinline__ void fadd2(unsigned long long &d, unsigned long long a) {
    asm("add.rn.f32x2 %0, %0, %1;" : "+l"(d) : "l"(a));
}
__device__ __forceinline__ unsigned long long pack2(float lo, float hi) {
    unsigned long long r;
    asm("mov.b64 %0, {%1, %2};" : "=l"(r) : "f"(lo), "f"(hi));
    return r;
}
__device__ __forceinline__ float pairsum(unsigned long long a) {
    float lo, hi;
    asm("mov.b64 {%0, %1}, %2;" : "=f"(lo), "=f"(hi) : "l"(a));
    return lo + hi;
}
__device__ __forceinline__ float ex2(float x) {
    float r; asm("ex2.approx.ftz.f32 %0, %1;" : "=f"(r) : "f"(x)); return r;
}
__device__ __forceinline__ float lg2(float x) {
    float r; asm("lg2.approx.ftz.f32 %0, %1;" : "=f"(r) : "f"(x)); return r;
}
__device__ __forceinline__ float wmax(float v) {
#pragma unroll
    for (int o = 16; o; o >>= 1) v = fmaxf(v, __shfl_xor_sync(0xffffffffu, v, o));
    return v;
}
__device__ __forceinline__ float wsum(float v) {
#pragma unroll
    for (int o = 16; o; o >>= 1) v += __shfl_xor_sync(0xffffffffu, v, o);
    return v;
}

// P-buffer float index for pair i: 8 floats per pair, 16B pad every 4 pairs
// (breaks the 4-way STS bank conflict; consumer LDS is uniform/broadcast so
// layout choice is free there).
#define FIDX(i) (8 * (i) + 4 * ((i) >> 2))

// ---------------------------------------------------------------------------
// One block per 4 batch rows, 128 threads; thread j owns output tag j with its
// Q row (log2 domain) in 128 registers. Per step the ONLY critical-path work
// is: matvec -> pairsum -> P = y*ec -> STS -> BAR. Everything else (normalizer
// refresh, fv materialization, boundary lse, ec for next step, feat prefetch
// depth 2) runs in the shadow of the matvec.
// ---------------------------------------------------------------------------
__global__ void __launch_bounds__(128, 1)
crf_kernel(const float* __restrict__ feats, const float* __restrict__ trans) {
    const int b0 = blockIdx.x * NB;
    const int j = threadIdx.x, lane = j & 31, wid = j >> 5;

    __shared__ __align__(16) float PI[2][576];        // padded P buffers
    __shared__ __align__(16) float wmbuf[2][NB][4];   // lagged warp-max slots
    __shared__ float bmv[NB][NEVT][4], bsv[NB][NEVT][4];

    // ---- start feat prefetches first (long latency) ----
    const size_t bstride = (size_t)BB * EE;
    const float* fp = feats + (size_t)b0 * EE + j;
    float fA[NB], fn[NB], fn2[NB];
#pragma unroll
    for (int b = 0; b < NB; b++) fA[b]  = fp[bstride + (size_t)b * EE];      // t=1 (u=0)
#pragma unroll
    for (int b = 0; b < NB; b++) fn[b]  = fp[2 * bstride + (size_t)b * EE];  // t=2 (u=1)
#pragma unroll
    for (int b = 0; b < NB; b++) fn2[b] = 0.0f;

    // ---- build Q row j (log2 domain) ----
    const float4* row = (const float4*)(trans + j * EE);
    float m = -3.4e38f;
#pragma unroll
    for (int i = 0; i < 32; i++) {
        float4 v = row[i];
        m = fmaxf(m, fmaxf(fmaxf(v.x, v.y), fmaxf(v.z, v.w)));
    }
    unsigned long long q[64];
#pragma unroll
    for (int i = 0; i < 32; i++) {
        float4 v = row[i];
        q[2 * i]     = pack2(ex2((v.x - m) * L2E), ex2((v.y - m) * L2E));
        q[2 * i + 1] = pack2(ex2((v.z - m) * L2E), ex2((v.w - m) * L2E));
    }
    const float mt2 = m * L2E;
    const float tl2 = trans[(EE - 1) * EE + j] * L2E;   // transitions[-1][j]

    float Gu[NB], Gm1[NB];
#pragma unroll
    for (int b = 0; b < NB; b++) {
        Gu[b] = (b0 + b == 0) ? 0.0f : (-10000.0f * L2E);  // init fv uniform per batch
        Gm1[b] = Gu[b];
    }
    if (lane == 0) {
#pragma unroll
        for (int b = 0; b < NB; b++) { wmbuf[0][b][wid] = Gu[b]; wmbuf[1][b][wid] = Gu[b]; }
    }

    // P for u=0: fv_init uniform == Ginit, so P = 2^(f0*L2E)
    float P[NB], ec[NB], ly[NB];
#pragma unroll
    for (int b = 0; b < NB; b++) { P[b] = ex2(fA[b] * L2E); ly[b] = 0.0f; }

    int t2 = 3, s2 = 2;                 // prefetch tracking: t(u+2), (u+2)%7
    const int wbase = FIDX(j >> 1) + (j & 1);

#pragma unroll 1
    for (int u = 0; u < 112; u++) {
        // publish this step's P, sync
        float* W = &PI[u & 1][wbase];
        W[0] = P[0]; W[2] = P[1]; W[4] = P[2]; W[6] = P[3];
        __syncthreads();

        // ---- shadow work (off critical path) ----
        float Gn[NB];
#pragma unroll
        for (int b = 0; b < NB; b++) {
            float4 w = *(const float4*)wmbuf[u & 1][b];
            Gn[b] = fmaxf(fmaxf(w.x, w.y), fmaxf(w.z, w.w));   // = G_{u+1} (lag-3 max)
        }
        if (u >= 1) {
            // materialize fv_{u-1}; publish warp max; boundary partials every 7th
            float fvp[NB], wm[NB];
#pragma unroll
            for (int b = 0; b < NB; b++) { fvp[b] = Gm1[b] + mt2 + ly[b]; wm[b] = wmax(fvp[b]); }
            if (lane == 0) {
#pragma unroll
                for (int b = 0; b < NB; b++) wmbuf[(u - 1) & 1][b][wid] = wm[b];
            }
            if ((u % 7) == 0) {         // u in {7,...,105}: boundary e = u/7
                int e = u / 7 - 1;
#pragma unroll
                for (int b = 0; b < NB; b++) {
                    float v  = fvp[b] + tl2;
                    float mm = wmax(v);
                    float ss = wsum(ex2(v - mm));
                    if (lane == 0) { bmv[b][e][wid] = mm; bsv[b][e][wid] = ss; }
                }
            }
        }
        // ec for step u+1: 2^(G_u + mt2 + f_{u+1}*L2E - G_{u+1})
#pragma unroll
        for (int b = 0; b < NB; b++)
            ec[b] = ex2(fmaf(fn[b], L2E, Gu[b] + mt2 - Gn[b]));
        // prefetch f_{u+2}
        if (u < 110) {
            size_t off = (size_t)t2 * bstride;
#pragma unroll
            for (int b = 0; b < NB; b++) fn2[b] = fp[off + (size_t)b * EE];
        }
        s2++; if (s2 == 7) { s2 = 0; t2 += 2; } else t2++;

        // ---- matvec: y_b[j] = sum_k Q[j][k] * P_b[k] ----
        unsigned long long a0[2] = {0, 0}, a1[2] = {0, 0};
        unsigned long long a2[2] = {0, 0}, a3[2] = {0, 0};
        const float* PB = PI[u & 1];
#pragma unroll
        for (int i = 0; i < 64; i++) {
            const float* base = PB + FIDX(i);               // compile-time offsets
            ulonglong2 u01 = *(const ulonglong2*)base;       // (b0 pair, b1 pair)
            ulonglong2 u23 = *(const ulonglong2*)(base + 4); // (b2 pair, b3 pair)
            ffma2(a0[i & 1], q[i], u01.x);
            ffma2(a1[i & 1], q[i], u01.y);
            ffma2(a2[i & 1], q[i], u23.x);
            ffma2(a3[i & 1], q[i], u23.y);
        }
        fadd2(a0[0], a0[1]); fadd2(a1[0], a1[1]);
        fadd2(a2[0], a2[1]); fadd2(a3[0], a3[1]);
        float y0 = pairsum(a0[0]), y1 = pairsum(a1[0]);
        float y2 = pairsum(a2[0]), y3 = pairsum(a3[0]);
        P[0] = y0 * ec[0]; P[1] = y1 * ec[1];       // critical path: one FMUL
        P[2] = y2 * ec[2]; P[3] = y3 * ec[3];
        ly[0] = lg2(y0); ly[1] = lg2(y1);           // lazy fv, consumed next step
        ly[2] = lg2(y2); ly[3] = lg2(y3);
#pragma unroll
        for (int b = 0; b < NB; b++) { Gm1[b] = Gu[b]; Gu[b] = Gn[b]; fn[b] = fn2[b]; }
    }

    // terminal partials from fv_111 = Gm1 + mt2 + ly
#pragma unroll
    for (int b = 0; b < NB; b++) {
        float v  = Gm1[b] + mt2 + ly[b] + tl2;
        float mm = wmax(v);
        float ss = wsum(ex2(v - mm));
        if (lane == 0) { bmv[b][NEVT - 1][wid] = mm; bsv[b][NEVT - 1][wid] = ss; }
    }
    __syncthreads();

    // combine deferred partials: 64 threads = 16 events x 4 batches
    if (j < 64) {
        int ev = j & 15, bt = j >> 4;
        float m0 = bmv[bt][ev][0], m1 = bmv[bt][ev][1];
        float m2 = bmv[bt][ev][2], m3 = bmv[bt][ev][3];
        float M = fmaxf(fmaxf(m0, m1), fmaxf(m2, m3));
        float ss = bsv[bt][ev][0] * ex2(m0 - M) + bsv[bt][ev][1] * ex2(m1 - M)
                 + bsv[bt][ev][2] * ex2(m2 - M) + bsv[bt][ev][3] * ex2(m3 - M);
        float l = M + lg2(ss);                 // per-event lse, log2 units
#pragma unroll
        for (int o = 1; o < 16; o <<= 1) l += __shfl_xor_sync(0xffffffffu, l, o);
        if (ev == 0) g_partial[b0 + bt] = l * LN2;
    }
}

// ---------------------------------------------------------------------------
__global__ void reduce_kernel(float* __restrict__ out) {
    int i = threadIdx.x;          // 512 threads
    float v = g_partial[i];
    v = wsum(v);
    __shared__ float s[16];
    if ((i & 31) == 0) s[i >> 5] = v;
    __syncthreads();
    if (i == 0) {
        float tot = 0.0f;
#pragma unroll
        for (int w = 0; w < 16; w++) tot += s[w];
        out[0] = tot * (1.0f / (float)(BB * NEVT));
    }
}

// ---------------------------------------------------------------------------
extern "C" void kernel_launch(void* const* d_in, const int* in_sizes, int n_in,
                              void* d_out, int out_size) {
    const float* feats = (const float*)d_in[0];
    const float* trans = (const float*)d_in[1];
    if (n_in >= 2 && in_sizes[0] == EE * EE) {   // defensive order check
        feats = (const float*)d_in[1];
        trans = (const float*)d_in[0];
    }
    crf_kernel<<<BB / NB, EE>>>(feats, trans);
    reduce_kernel<<<1, BB>>>((float*)d_out);
}